// round 15
// baseline (speedup 1.0000x reference)
#include <cuda_runtime.h>
#include <cuda_bf16.h>
#include <cstdint>

#define BB 2
#define NQ 256
#define ED 512
#define HH 150
#define HP 152

#define P1 272            // B pitch (bytes)
#define PH 304            // HtB/W2s pitch (bytes)
#define PG2 1040          // g staging pitch (bytes)

// ---------------- device scratch ----------------
__device__ __nv_bfloat16 d_w1ctb[HP*ED];      // W1c^T bf16 [h][e]
__device__ __nv_bfloat16 d_w2t[HP*HP];        // W2^T bf16 [o][k]
__device__ float         d_hip[2*BB*NQ*HP];   // hi+b1 partials
__device__ float         d_hjp[2*BB*NQ*HP];   // hj partials

// ---------------- smem layout (bytes), per 256-thread half-CTA ----------------
#define SM_HIS  0                       // 24*152*2 = 7296 (rows 0-7: I, 8-23: J)
#define SM_HJS  7296                    // 7296 -> 14592
#define SM_B2S  14592                   // 608
#define SM_W3S  15200                   // 608
#define SM_MIS  15808                   // 64
#define SM_MJS  15872                   // 64
#define SM_U    15936
// stage-1: [G 24*1040=24960][B 41344] = 66304
#define OFF_G   0
#define OFF_B   24960
// stage-2 aliases over the union
#define OFF_W2  0                       // 46208
#define OFF_HB  46208                   // 128*304 = 38912 -> 85120
#define SMEM_BYTES (SM_U + 85120)       // 101056  (2 CTAs/SM: 202112 < 228K)

__device__ __forceinline__ uint32_t smem_u32(const void* p) {
    uint32_t a;
    asm("{ .reg .u64 t; cvta.to.shared.u64 t, %1; cvt.u32.u64 %0, t; }" : "=r"(a) : "l"(p));
    return a;
}
__device__ __forceinline__ void ldsm_x4(uint32_t& r0, uint32_t& r1, uint32_t& r2, uint32_t& r3,
                                        uint32_t addr) {
    asm volatile("ldmatrix.sync.aligned.m8n8.x4.shared.b16 {%0,%1,%2,%3}, [%4];"
                 : "=r"(r0), "=r"(r1), "=r"(r2), "=r"(r3) : "r"(addr));
}
__device__ __forceinline__ void ldsm_x2(uint32_t& r0, uint32_t& r1, uint32_t addr) {
    asm volatile("ldmatrix.sync.aligned.m8n8.x2.shared.b16 {%0,%1}, [%2];"
                 : "=r"(r0), "=r"(r1) : "r"(addr));
}
__device__ __forceinline__ void ldsm_x1(uint32_t& r0, uint32_t addr) {
    asm volatile("ldmatrix.sync.aligned.m8n8.x1.shared.b16 {%0}, [%1];"
                 : "=r"(r0) : "r"(addr));
}
__device__ __forceinline__ void mma16816(float* d, uint32_t a0, uint32_t a1, uint32_t a2,
                                         uint32_t a3, uint32_t b0, uint32_t b1) {
    asm volatile("mma.sync.aligned.m16n8k16.row.col.f32.bf16.bf16.f32 "
                 "{%0,%1,%2,%3}, {%4,%5,%6,%7}, {%8,%9}, {%0,%1,%2,%3};"
                 : "+f"(d[0]), "+f"(d[1]), "+f"(d[2]), "+f"(d[3])
                 : "r"(a0), "r"(a1), "r"(a2), "r"(a3), "r"(b0), "r"(b1));
}
__device__ __forceinline__ void mma16808(float* d, uint32_t a0, uint32_t a1, uint32_t b0) {
    asm volatile("mma.sync.aligned.m16n8k8.row.col.f32.bf16.bf16.f32 "
                 "{%0,%1,%2,%3}, {%4,%5}, {%6}, {%0,%1,%2,%3};"
                 : "+f"(d[0]), "+f"(d[1]), "+f"(d[2]), "+f"(d[3])
                 : "r"(a0), "r"(a1), "r"(b0));
}
__device__ __forceinline__ uint32_t mulbf2(uint32_t a, uint32_t b) {
    uint32_t r;
    asm("mul.bf16x2 %0, %1, %2;" : "=r"(r) : "r"(a), "r"(b));
    return r;
}
__device__ __forceinline__ float2 bf2_to_f2(uint32_t u) {
    __nv_bfloat162 h = *(__nv_bfloat162*)&u;
    return __bfloat1622float2(h);
}
__device__ __forceinline__ uint32_t pack_bf2(float x, float y) {
    __nv_bfloat162 p = __floats2bfloat162_rn(x, y);
    return *(uint32_t*)&p;
}

// ---------------- prekernels (unchanged) ----------------
__global__ void prep_w1ct(const float* __restrict__ W1) {
    __shared__ float tile[32][33];
    int e0 = blockIdx.x * 32, h0 = blockIdx.y * 32;
    int tx = threadIdx.x, ty = threadIdx.y;
    int h = h0 + tx, e = e0 + ty;
    tile[ty][tx] = (h < HH) ? W1[(size_t)(2*ED + e)*HH + h] : 0.f;
    __syncthreads();
    int ho = h0 + ty, eo = e0 + tx;
    if (ho < HP) d_w1ctb[ho*ED + eo] = __float2bfloat16(tile[tx][ty]);
}
__global__ void prep_w2t(const float* __restrict__ W2) {
    int o = blockIdx.x, k = threadIdx.x;
    float v = (o < HH && k < HH) ? W2[k*HH + o] : 0.f;
    d_w2t[o*HP + k] = __float2bfloat16(v);
}
__global__ void prep_hihj(const float* __restrict__ g, const float* __restrict__ W1,
                          const float* __restrict__ b1) {
    __shared__ float gs[8][256];
    __shared__ float red[4][8][160];
    const int n0 = blockIdx.x * 8, b = blockIdx.y, z = blockIdx.z;
    const int h = threadIdx.x, s = threadIdx.y;
    const int t = s*160 + h;
    for (int idx = t; idx < 8*256; idx += 640) {
        int row = idx >> 8, e = idx & 255;
        gs[row][e] = g[(size_t)(b*NQ + n0 + row)*ED + z*256 + e];
    }
    __syncthreads();
    float a1[8], a2[8];
    #pragma unroll
    for (int r = 0; r < 8; r++) { a1[r] = 0.f; a2[r] = 0.f; }
    if (h < HH) {
        const int ebase = z*256 + s*64;
        const float* pa = W1 + (size_t)ebase*HH + h;
        const float* pb = W1 + (size_t)(ED + ebase)*HH + h;
        const float* gp = &gs[0][s*64];
        #pragma unroll 4
        for (int el = 0; el < 64; el++) {
            float wa = pa[(size_t)el*HH];
            float wb = pb[(size_t)el*HH];
            #pragma unroll
            for (int r = 0; r < 8; r++) {
                float ge = gp[r*256 + el];
                a1[r] = fmaf(ge, wa, a1[r]);
                a2[r] = fmaf(ge, wb, a2[r]);
            }
        }
    }
    #pragma unroll
    for (int r = 0; r < 8; r++) red[s][r][h] = a1[r];
    __syncthreads();
    if (s == 0 && h < HP) {
        #pragma unroll
        for (int r = 0; r < 8; r++) {
            float v = 0.f;
            if (h < HH) {
                v = red[0][r][h] + red[1][r][h] + red[2][r][h] + red[3][r][h];
                if (z == 0) v += b1[h];
            }
            d_hip[z*(BB*NQ*HP) + (b*NQ + n0 + r)*HP + h] = v;
        }
    }
    __syncthreads();
    #pragma unroll
    for (int r = 0; r < 8; r++) red[s][r][h] = a2[r];
    __syncthreads();
    if (s == 0 && h < HP) {
        #pragma unroll
        for (int r = 0; r < 8; r++) {
            float v = 0.f;
            if (h < HH)
                v = red[0][r][h] + red[1][r][h] + red[2][r][h] + red[3][r][h];
            d_hjp[z*(BB*NQ*HP) + (b*NQ + n0 + r)*HP + h] = v;
        }
    }
}

// ---------------- main kernel: half-block CTAs (8i x 16j), 2 CTAs/SM ----------------
__global__ __launch_bounds__(256, 2)
void pair_half_kernel(const float* __restrict__ g,
                      const float* __restrict__ m,
                      const float* __restrict__ b2,
                      const float* __restrict__ W3,
                      const float* __restrict__ b3,
                      float* __restrict__ out) {
    extern __shared__ char smc[];
    const int t = threadIdx.x, w = t >> 5, lane = t & 31;
    const int b = blockIdx.y;
    const int pbx = blockIdx.x >> 1, half = blockIdx.x & 1;
    int I = 0, rem = pbx;
    while (rem >= 16 - I) { rem -= 16 - I; I++; }
    const int J = I + rem;
    const int i0h = (I << 4) + half*8;    // this CTA's 8 i-rows
    const int j0  = J << 4;
    const bool diag = (I == J);

    __nv_bfloat16* his = (__nv_bfloat16*)(smc + SM_HIS);   // rows 0-7: I, 8-23: J
    __nv_bfloat16* hjs = (__nv_bfloat16*)(smc + SM_HJS);
    float* b2s = (float*)(smc + SM_B2S);
    float* w3s = (float*)(smc + SM_W3S);
    float* mIs = (float*)(smc + SM_MIS);
    float* mJs = (float*)(smc + SM_MJS);
    char* Gc  = smc + SM_U + OFF_G;
    char* Bt  = smc + SM_U + OFF_B;
    char* W2s = smc + SM_U + OFF_W2;      // alias (post stage-1)
    char* HtB = smc + SM_U + OFF_HB;      // alias (post stage-1)

    // ---- tables: 8 I rows + 16 J rows ----
    for (int idx = t; idx < 24*HP; idx += 256) {
        int r = idx / HP, h = idx - r*HP;
        int row = (r < 8) ? (i0h + r) : (j0 + r - 8);
        int o = (b*NQ + row)*HP + h;
        his[idx] = __float2bfloat16(d_hip[o] + d_hip[BB*NQ*HP + o]);
        hjs[idx] = __float2bfloat16(d_hjp[o] + d_hjp[BB*NQ*HP + o]);
    }
    for (int idx = t; idx < HP; idx += 256) {
        b2s[idx] = (idx < HH) ? b2[idx] : 0.f;
        w3s[idx] = (idx < HH) ? W3[idx] : 0.f;
    }
    if (t < 8)            mIs[t]      = m[b*NQ + i0h + t];
    else if (t < 24)      mJs[t - 8]  = m[b*NQ + j0 + (t - 8)];

    // ---- stage g (24 rows x 512 cols) into G ----
    if (t < 192) {
        int r = t >> 3;
        int grow = (r < 8) ? (i0h + r) : (j0 + (r - 8));
        int c0 = (t & 7) * 64;
        const float* gp = g + (size_t)(b*NQ + grow)*ED + c0;
        char* dst = Gc + r*PG2 + c0*2;
        #pragma unroll
        for (int q = 0; q < 8; q++) {
            float4 va = *(const float4*)(gp + q*8);
            float4 vb = *(const float4*)(gp + q*8 + 4);
            uint4 v = { pack_bf2(va.x, va.y), pack_bf2(va.z, va.w),
                        pack_bf2(vb.x, vb.y), pack_bf2(vb.z, vb.w) };
            *(uint4*)(dst + q*16) = v;
        }
    }

    float acc[19][4];
    #pragma unroll
    for (int n = 0; n < 19; n++)
        #pragma unroll
        for (int k = 0; k < 4; k++) acc[n][k] = 0.f;

    // A-fragment pointers: warp w = i-row w; gj rows 8..23
    const char* gip  = Gc + w*PG2 + (lane & 3)*4;
    const char* gjAp = Gc + (8 + (lane >> 2))*PG2 + (lane & 3)*4;
    const char* gjBp = gjAp + 8*PG2;
    const uint32_t Ba = smem_u32(Bt);
    const uint32_t brow  = (lane & 7) + ((lane >> 4) << 3);
    const uint32_t bkoff = ((lane >> 3) & 1) << 4;

    // ---- stage 1: 4 K-chunks; B load serialized per chunk (hidden by co-CTA) ----
    for (int c = 0; c < 4; c++) {
        const __nv_bfloat16* bsrc = d_w1ctb + c*128;
        #pragma unroll
        for (int q = 0; q < 10; q++) {
            int idx = q*256 + t;
            if (idx < 2432) {
                int row = idx >> 4, c16 = idx & 15;
                *(uint4*)(Bt + row*P1 + c16*16) = *(const uint4*)(bsrc + row*ED + c16*8);
            }
        }
        __syncthreads();
        #pragma unroll
        for (int ks = 0; ks < 8; ks++) {
            const int eb = c*256 + ks*32;
            uint32_t gi0 = *(const uint32_t*)(gip + eb);
            uint32_t gi1 = *(const uint32_t*)(gip + eb + 16);
            uint32_t ga0 = *(const uint32_t*)(gjAp + eb);
            uint32_t ga1 = *(const uint32_t*)(gjAp + eb + 16);
            uint32_t gb0 = *(const uint32_t*)(gjBp + eb);
            uint32_t gb1 = *(const uint32_t*)(gjBp + eb + 16);
            uint32_t a0 = mulbf2(gi0, ga0);
            uint32_t a1 = mulbf2(gi0, gb0);
            uint32_t a2 = mulbf2(gi1, ga1);
            uint32_t a3 = mulbf2(gi1, gb1);
            uint32_t bb = Ba + brow*P1 + bkoff + ks*32;
            #pragma unroll
            for (int np = 0; np < 9; np++) {
                uint32_t b0, b1r, b2r, b3r;
                ldsm_x4(b0, b1r, b2r, b3r, bb + np*(16*P1));
                mma16816(acc[2*np],     a0, a1, a2, a3, b0, b1r);
                mma16816(acc[2*np + 1], a0, a1, a2, a3, b2r, b3r);
            }
            uint32_t b0, b1r;
            ldsm_x2(b0, b1r, Ba + (144 + (lane & 7))*P1 + bkoff + ks*32);
            mma16816(acc[18], a0, a1, a2, a3, b0, b1r);
        }
        __syncthreads();
    }

    // ---- epilogue 1: hA frags in regs; hB -> HtB (rows jj*8 + w); W2 -> W2s ----
    uint32_t hA[19][2];
    {
        #pragma unroll
        for (int q = 0; q < 12; q++) {
            int idx = q*256 + t;
            if (idx < HP*19) {
                int row = idx / 19, c16 = idx - row*19;
                *(uint4*)(W2s + row*PH + c16*16) = *(const uint4*)(d_w2t + row*HP + c16*8);
            }
        }
        const __nv_bfloat16* hiIr = his + w*HP;
        const __nv_bfloat16* hjIr = hjs + w*HP;
        const int jlo = lane >> 2, jhi = jlo + 8;
        const __nv_bfloat16* hjJl = hjs + (8 + jlo)*HP;
        const __nv_bfloat16* hjJh = hjs + (8 + jhi)*HP;
        const __nv_bfloat16* hiJl = his + (8 + jlo)*HP;
        const __nv_bfloat16* hiJh = his + (8 + jhi)*HP;
        char* rowBlo = HtB + (jlo*8 + w)*PH;
        char* rowBhi = HtB + (jhi*8 + w)*PH;
        #pragma unroll
        for (int nt = 0; nt < 19; nt++) {
            int col = nt*8 + (lane & 3)*2;
            float2 hiI = bf2_to_f2(*(const uint32_t*)(hiIr + col));
            float2 hjl = bf2_to_f2(*(const uint32_t*)(hjJl + col));
            float2 hjh = bf2_to_f2(*(const uint32_t*)(hjJh + col));
            hA[nt][0] = pack_bf2(fmaxf(acc[nt][0] + hiI.x + hjl.x, 0.f),
                                 fmaxf(acc[nt][1] + hiI.y + hjl.y, 0.f));
            hA[nt][1] = pack_bf2(fmaxf(acc[nt][2] + hiI.x + hjh.x, 0.f),
                                 fmaxf(acc[nt][3] + hiI.y + hjh.y, 0.f));
            if (!diag) {
                float2 hjI = bf2_to_f2(*(const uint32_t*)(hjIr + col));
                float2 hil = bf2_to_f2(*(const uint32_t*)(hiJl + col));
                float2 hih = bf2_to_f2(*(const uint32_t*)(hiJh + col));
                *(uint32_t*)(rowBlo + col*2) =
                    pack_bf2(fmaxf(acc[nt][0] + hil.x + hjI.x, 0.f),
                             fmaxf(acc[nt][1] + hil.y + hjI.y, 0.f));
                *(uint32_t*)(rowBhi + col*2) =
                    pack_bf2(fmaxf(acc[nt][2] + hih.x + hjI.x, 0.f),
                             fmaxf(acc[nt][3] + hih.y + hjI.y, 0.f));
            }
        }
    }
    __syncthreads();   // W2s + HtB ready

    // ---- stage 2 ----
    const uint32_t W2a  = smem_u32(W2s);
    const uint32_t HtBa = smem_u32(HtB);
    const float b3v = b3[0];

    auto stage2 = [&](bool useHtB, int pass) {
        float sl = 0.f, sh = 0.f;
        #pragma unroll
        for (int hf = 0; hf < 2; hf++) {
            float a2c[10][4];
            #pragma unroll
            for (int n = 0; n < 10; n++)
                #pragma unroll
                for (int k = 0; k < 4; k++) a2c[n][k] = 0.f;

            #pragma unroll
            for (int ks = 0; ks < 9; ks++) {
                uint32_t a0, a1, a2, a3;
                if (useHtB) {
                    uint32_t ab = HtBa + (w*16 + (lane & 15))*PH + ((lane >> 4) << 4) + ks*32;
                    ldsm_x4(a0, a1, a2, a3, ab);
                } else {
                    a0 = hA[2*ks][0]; a1 = hA[2*ks][1];
                    a2 = hA[2*ks + 1][0]; a3 = hA[2*ks + 1][1];
                }
                if (hf == 0) {
                    uint32_t bb = W2a + brow*PH + bkoff + ks*32;
                    #pragma unroll
                    for (int np = 0; np < 5; np++) {
                        uint32_t b0, b1r, b2r, b3r;
                        ldsm_x4(b0, b1r, b2r, b3r, bb + np*(16*PH));
                        mma16816(a2c[2*np],     a0, a1, a2, a3, b0, b1r);
                        mma16816(a2c[2*np + 1], a0, a1, a2, a3, b2r, b3r);
                    }
                } else {
                    uint32_t bb = W2a + (80 + brow)*PH + bkoff + ks*32;
                    #pragma unroll
                    for (int np = 0; np < 4; np++) {
                        uint32_t b0, b1r, b2r, b3r;
                        ldsm_x4(b0, b1r, b2r, b3r, bb + np*(16*PH));
                        mma16816(a2c[2*np],     a0, a1, a2, a3, b0, b1r);
                        mma16816(a2c[2*np + 1], a0, a1, a2, a3, b2r, b3r);
                    }
                    uint32_t b0, b1r;
                    ldsm_x2(b0, b1r, W2a + (144 + (lane & 7))*PH + bkoff + ks*32);
                    mma16816(a2c[8], a0, a1, a2, a3, b0, b1r);
                }
            }
            {   // k8 tail (cols 144-151, byte 288)
                uint32_t ta0, ta1;
                if (useHtB) ldsm_x2(ta0, ta1, HtBa + (w*16 + (lane & 15))*PH + 288);
                else { ta0 = hA[18][0]; ta1 = hA[18][1]; }
                if (hf == 0) {
                    #pragma unroll
                    for (int q = 0; q < 2; q++) {
                        uint32_t b0, b1r, b2r, b3r;
                        ldsm_x4(b0, b1r, b2r, b3r,
                                W2a + (uint32_t)((q*32 + (lane >> 3)*8 + (lane & 7))*PH + 288));
                        mma16808(a2c[4*q + 0], ta0, ta1, b0);
                        mma16808(a2c[4*q + 1], ta0, ta1, b1r);
                        mma16808(a2c[4*q + 2], ta0, ta1, b2r);
                        mma16808(a2c[4*q + 3], ta0, ta1, b3r);
                    }
                    uint32_t b0, b1r;
                    ldsm_x2(b0, b1r,
                            W2a + (uint32_t)((64 + ((lane >> 3) & 1)*8 + (lane & 7))*PH + 288));
                    mma16808(a2c[8], ta0, ta1, b0);
                    mma16808(a2c[9], ta0, ta1, b1r);
                } else {
                    #pragma unroll
                    for (int q = 0; q < 2; q++) {
                        uint32_t b0, b1r, b2r, b3r;
                        ldsm_x4(b0, b1r, b2r, b3r,
                                W2a + (uint32_t)((80 + q*32 + (lane >> 3)*8 + (lane & 7))*PH + 288));
                        mma16808(a2c[4*q + 0], ta0, ta1, b0);
                        mma16808(a2c[4*q + 1], ta0, ta1, b1r);
                        mma16808(a2c[4*q + 2], ta0, ta1, b2r);
                        mma16808(a2c[4*q + 3], ta0, ta1, b3r);
                    }
                    uint32_t bx;
                    ldsm_x1(bx, W2a + (uint32_t)((144 + (lane & 7))*PH + 288));
                    mma16808(a2c[8], ta0, ta1, bx);
                }
            }
            const int ntl = hf ? 9 : 10;
            #pragma unroll
            for (int nt = 0; nt < 10; nt++) {
                if (nt >= ntl) break;
                int col = hf*80 + nt*8 + (lane & 3)*2;
                sl = fmaf(fmaxf(a2c[nt][0] + b2s[col],     0.f), w3s[col],     sl);
                sl = fmaf(fmaxf(a2c[nt][1] + b2s[col + 1], 0.f), w3s[col + 1], sl);
                sh = fmaf(fmaxf(a2c[nt][2] + b2s[col],     0.f), w3s[col],     sh);
                sh = fmaf(fmaxf(a2c[nt][3] + b2s[col + 1], 0.f), w3s[col + 1], sh);
            }
        }
        sl += __shfl_xor_sync(0xFFFFFFFF, sl, 1);
        sl += __shfl_xor_sync(0xFFFFFFFF, sl, 2);
        sh += __shfl_xor_sync(0xFFFFFFFF, sh, 1);
        sh += __shfl_xor_sync(0xFFFFFFFF, sh, 2);
        if ((lane & 3) == 0) {
            int q = lane >> 2;    // 0..7
            if (pass == 0) {
                // rows: frag row q -> j0+q (sl), j0+q+8 (sh); i = i0h + w
                float rl = (mIs[w] + mJs[q]     + sl + b3v) * (1.0f/3.0f);
                float rh = (mIs[w] + mJs[q + 8] + sh + b3v) * (1.0f/3.0f);
                out[(size_t)(b*NQ + i0h + w)*NQ + j0 + q]     = rl;
                out[(size_t)(b*NQ + i0h + w)*NQ + j0 + q + 8] = rh;
            } else {
                // HtB rows w*16 + r, r = jjloc*8 + ii: sl r=q -> jj=2w, ii=q; sh r=q+8 -> jj=2w+1, ii=q
                float rl = (mJs[2*w]     + mIs[q] + sl + b3v) * (1.0f/3.0f);
                float rh = (mJs[2*w + 1] + mIs[q] + sh + b3v) * (1.0f/3.0f);
                out[(size_t)(b*NQ + j0 + 2*w)*NQ     + i0h + q] = rl;
                out[(size_t)(b*NQ + j0 + 2*w + 1)*NQ + i0h + q] = rh;
            }
        }
    };

    stage2(false, 0);
    if (!diag) {
        __syncwarp();
        stage2(true, 1);
    }
}

// ---------------------------------------------------------------------------
extern "C" void kernel_launch(void* const* d_in, const int* in_sizes, int n_in,
                              void* d_out, int out_size) {
    const float* g  = (const float*)d_in[0];
    const float* m  = (const float*)d_in[1];
    const float* W1 = (const float*)d_in[2];
    const float* b1 = (const float*)d_in[3];
    const float* W2 = (const float*)d_in[4];
    const float* b2 = (const float*)d_in[5];
    const float* W3 = (const float*)d_in[6];
    const float* b3 = (const float*)d_in[7];
    float* out = (float*)d_out;

    cudaFuncSetAttribute(pair_half_kernel,
                         cudaFuncAttributeMaxDynamicSharedMemorySize, SMEM_BYTES);

    prep_w1ct<<<dim3(ED/32, 5), dim3(32, 32)>>>(W1);
    prep_w2t<<<HP, HP>>>(W2);
    prep_hihj<<<dim3(NQ/8, BB, 2), dim3(160, 4)>>>(g, W1, b1);
    pair_half_kernel<<<dim3(272, BB), 256, SMEM_BYTES>>>(g, m, b2, W3, b3, out);
}

// round 16
// speedup vs baseline: 1.1854x; 1.1854x over previous
#include <cuda_runtime.h>
#include <cuda_bf16.h>
#include <cstdint>

#define BB 2
#define NQ 256
#define ED 512
#define HH 150
#define HP 152

#define P1 272            // B pitch (bytes)
#define PH 304            // HtB/W2s pitch (bytes)
#define PG2 1040          // g staging pitch (bytes)

// ---------------- device scratch ----------------
__device__ __nv_bfloat16 d_w1ctb[HP*ED];      // W1c^T bf16 [h][e]
__device__ __nv_bfloat16 d_w2t[HP*HP];        // W2^T bf16 [o][k]
__device__ float         d_hip[2*BB*NQ*HP];   // hi+b1 partials
__device__ float         d_hjp[2*BB*NQ*HP];   // hj partials

// ---------------- smem layout (bytes) ----------------
#define SM_HIS  0                       // 9728
#define SM_HJS  9728                    // -> 19456
#define SM_B2S  19456                   // 608
#define SM_W3S  20064                   // 608
#define SM_MIS  20672                   // 64
#define SM_MJS  20736                   // 64
#define SM_U    20800
// stage-1: [G 33280][B0 41344][B1 41344] = 115968
#define OFF_G   0
#define OFF_B0  33280
#define OFF_B1b 74624
// stage-2 aliases (all stage-1 regions dead)
#define OFF_W2  0                       // 46208
#define OFF_HB  46208                   // 77824 -> 124032
#define SMEM_BYTES (SM_U + 124032)      // 144832

__device__ __forceinline__ uint32_t smem_u32(const void* p) {
    uint32_t a;
    asm("{ .reg .u64 t; cvta.to.shared.u64 t, %1; cvt.u32.u64 %0, t; }" : "=r"(a) : "l"(p));
    return a;
}
__device__ __forceinline__ void ldsm_x4(uint32_t& r0, uint32_t& r1, uint32_t& r2, uint32_t& r3,
                                        uint32_t addr) {
    asm volatile("ldmatrix.sync.aligned.m8n8.x4.shared.b16 {%0,%1,%2,%3}, [%4];"
                 : "=r"(r0), "=r"(r1), "=r"(r2), "=r"(r3) : "r"(addr));
}
__device__ __forceinline__ void ldsm_x2(uint32_t& r0, uint32_t& r1, uint32_t addr) {
    asm volatile("ldmatrix.sync.aligned.m8n8.x2.shared.b16 {%0,%1}, [%2];"
                 : "=r"(r0), "=r"(r1) : "r"(addr));
}
__device__ __forceinline__ void ldsm_x1(uint32_t& r0, uint32_t addr) {
    asm volatile("ldmatrix.sync.aligned.m8n8.x1.shared.b16 {%0}, [%1];"
                 : "=r"(r0) : "r"(addr));
}
__device__ __forceinline__ void mma16816(float* d, uint32_t a0, uint32_t a1, uint32_t a2,
                                         uint32_t a3, uint32_t b0, uint32_t b1) {
    asm volatile("mma.sync.aligned.m16n8k16.row.col.f32.bf16.bf16.f32 "
                 "{%0,%1,%2,%3}, {%4,%5,%6,%7}, {%8,%9}, {%0,%1,%2,%3};"
                 : "+f"(d[0]), "+f"(d[1]), "+f"(d[2]), "+f"(d[3])
                 : "r"(a0), "r"(a1), "r"(a2), "r"(a3), "r"(b0), "r"(b1));
}
__device__ __forceinline__ void mma16808(float* d, uint32_t a0, uint32_t a1, uint32_t b0) {
    asm volatile("mma.sync.aligned.m16n8k8.row.col.f32.bf16.bf16.f32 "
                 "{%0,%1,%2,%3}, {%4,%5}, {%6}, {%0,%1,%2,%3};"
                 : "+f"(d[0]), "+f"(d[1]), "+f"(d[2]), "+f"(d[3])
                 : "r"(a0), "r"(a1), "r"(b0));
}
__device__ __forceinline__ uint32_t mulbf2(uint32_t a, uint32_t b) {
    uint32_t r;
    asm("mul.bf16x2 %0, %1, %2;" : "=r"(r) : "r"(a), "r"(b));
    return r;
}
__device__ __forceinline__ float2 bf2_to_f2(uint32_t u) {
    __nv_bfloat162 h = *(__nv_bfloat162*)&u;
    return __bfloat1622float2(h);
}
__device__ __forceinline__ uint32_t pack_bf2(float x, float y) {
    __nv_bfloat162 p = __floats2bfloat162_rn(x, y);
    return *(uint32_t*)&p;
}

// ---------------- prekernels (unchanged) ----------------
__global__ void prep_w1ct(const float* __restrict__ W1) {
    __shared__ float tile[32][33];
    int e0 = blockIdx.x * 32, h0 = blockIdx.y * 32;
    int tx = threadIdx.x, ty = threadIdx.y;
    int h = h0 + tx, e = e0 + ty;
    tile[ty][tx] = (h < HH) ? W1[(size_t)(2*ED + e)*HH + h] : 0.f;
    __syncthreads();
    int ho = h0 + ty, eo = e0 + tx;
    if (ho < HP) d_w1ctb[ho*ED + eo] = __float2bfloat16(tile[tx][ty]);
}
__global__ void prep_w2t(const float* __restrict__ W2) {
    int o = blockIdx.x, k = threadIdx.x;
    float v = (o < HH && k < HH) ? W2[k*HH + o] : 0.f;
    d_w2t[o*HP + k] = __float2bfloat16(v);
}
__global__ void prep_hihj(const float* __restrict__ g, const float* __restrict__ W1,
                          const float* __restrict__ b1) {
    __shared__ float gs[8][256];
    __shared__ float red[4][8][160];
    const int n0 = blockIdx.x * 8, b = blockIdx.y, z = blockIdx.z;
    const int h = threadIdx.x, s = threadIdx.y;
    const int t = s*160 + h;
    for (int idx = t; idx < 8*256; idx += 640) {
        int row = idx >> 8, e = idx & 255;
        gs[row][e] = g[(size_t)(b*NQ + n0 + row)*ED + z*256 + e];
    }
    __syncthreads();
    float a1[8], a2[8];
    #pragma unroll
    for (int r = 0; r < 8; r++) { a1[r] = 0.f; a2[r] = 0.f; }
    if (h < HH) {
        const int ebase = z*256 + s*64;
        const float* pa = W1 + (size_t)ebase*HH + h;
        const float* pb = W1 + (size_t)(ED + ebase)*HH + h;
        const float* gp = &gs[0][s*64];
        #pragma unroll 4
        for (int el = 0; el < 64; el++) {
            float wa = pa[(size_t)el*HH];
            float wb = pb[(size_t)el*HH];
            #pragma unroll
            for (int r = 0; r < 8; r++) {
                float ge = gp[r*256 + el];
                a1[r] = fmaf(ge, wa, a1[r]);
                a2[r] = fmaf(ge, wb, a2[r]);
            }
        }
    }
    #pragma unroll
    for (int r = 0; r < 8; r++) red[s][r][h] = a1[r];
    __syncthreads();
    if (s == 0 && h < HP) {
        #pragma unroll
        for (int r = 0; r < 8; r++) {
            float v = 0.f;
            if (h < HH) {
                v = red[0][r][h] + red[1][r][h] + red[2][r][h] + red[3][r][h];
                if (z == 0) v += b1[h];
            }
            d_hip[z*(BB*NQ*HP) + (b*NQ + n0 + r)*HP + h] = v;
        }
    }
    __syncthreads();
    #pragma unroll
    for (int r = 0; r < 8; r++) red[s][r][h] = a2[r];
    __syncthreads();
    if (s == 0 && h < HP) {
        #pragma unroll
        for (int r = 0; r < 8; r++) {
            float v = 0.f;
            if (h < HH)
                v = red[0][r][h] + red[1][r][h] + red[2][r][h] + red[3][r][h];
            d_hjp[z*(BB*NQ*HP) + (b*NQ + n0 + r)*HP + h] = v;
        }
    }
}

// ---------------- main kernel ----------------
__global__ __launch_bounds__(512, 1)
void pair_frag3_kernel(const float* __restrict__ g,
                       const float* __restrict__ m,
                       const float* __restrict__ b2,
                       const float* __restrict__ W3,
                       const float* __restrict__ b3,
                       float* __restrict__ out) {
    extern __shared__ char smc[];
    const int t = threadIdx.x, w = t >> 5, lane = t & 31;
    const int b = blockIdx.y;
    int I = 0, rem = blockIdx.x;
    while (rem >= 16 - I) { rem -= 16 - I; I++; }
    const int J = I + rem;
    const int i0 = I << 4, j0 = J << 4;
    const bool diag = (I == J);

    __nv_bfloat16* his = (__nv_bfloat16*)(smc + SM_HIS);
    __nv_bfloat16* hjs = (__nv_bfloat16*)(smc + SM_HJS);
    float* b2s = (float*)(smc + SM_B2S);
    float* w3s = (float*)(smc + SM_W3S);
    float* mIs = (float*)(smc + SM_MIS);
    float* mJs = (float*)(smc + SM_MJS);
    char* Gc  = smc + SM_U + OFF_G;
    char* Bp[2] = { smc + SM_U + OFF_B0, smc + SM_U + OFF_B1b };
    char* W2s = smc + SM_U + OFF_W2;
    char* HtB = smc + SM_U + OFF_HB;

    // ---- tables ----
    for (int idx = t; idx < 16*HP; idx += 512) {
        int r = idx / HP, h = idx - r*HP;
        int io = (b*NQ + i0 + r)*HP + h;
        int jo = (b*NQ + j0 + r)*HP + h;
        his[r*HP + h]        = __float2bfloat16(d_hip[io] + d_hip[BB*NQ*HP + io]);
        his[(16 + r)*HP + h] = __float2bfloat16(d_hip[jo] + d_hip[BB*NQ*HP + jo]);
        hjs[r*HP + h]        = __float2bfloat16(d_hjp[io] + d_hjp[BB*NQ*HP + io]);
        hjs[(16 + r)*HP + h] = __float2bfloat16(d_hjp[jo] + d_hjp[BB*NQ*HP + jo]);
    }
    for (int idx = t; idx < HP; idx += 512) {
        b2s[idx] = (idx < HH) ? b2[idx] : 0.f;
        w3s[idx] = (idx < HH) ? W3[idx] : 0.f;
    }
    if (t < 16)       mIs[t]      = m[b*NQ + i0 + t];
    else if (t < 32)  mJs[t - 16] = m[b*NQ + j0 + (t - 16)];

    // ---- stage g into G ----
    {
        int r = t >> 4;
        int grow = (r < 16) ? (i0 + r) : (j0 + (r - 16));
        int c0 = (t & 15) * 32;
        const float* gp = g + (size_t)(b*NQ + grow)*ED + c0;
        char* dst = Gc + r*PG2 + c0*2;
        #pragma unroll
        for (int q = 0; q < 4; q++) {
            float4 va = *(const float4*)(gp + q*8);
            float4 vb = *(const float4*)(gp + q*8 + 4);
            uint4 v = { pack_bf2(va.x, va.y), pack_bf2(va.z, va.w),
                        pack_bf2(vb.x, vb.y), pack_bf2(vb.z, vb.w) };
            *(uint4*)(dst + q*16) = v;
        }
    }
    // ---- B(0) ----
    #pragma unroll
    for (int q = 0; q < 5; q++) {
        int idx = q*512 + t;
        if (idx < 2432) {
            int row = idx >> 4, c16 = idx & 15;
            *(uint4*)(Bp[0] + row*P1 + c16*16) = *(const uint4*)(d_w1ctb + row*ED + c16*8);
        }
    }
    __syncthreads();

    float acc[19][4];
    #pragma unroll
    for (int n = 0; n < 19; n++)
        #pragma unroll
        for (int k = 0; k < 4; k++) acc[n][k] = 0.f;

    const char* gip  = Gc + w*PG2 + (lane & 3)*4;
    const char* gjAp = Gc + (16 + (lane >> 2))*PG2 + (lane & 3)*4;
    const char* gjBp = gjAp + 8*PG2;
    const uint32_t brow  = (lane & 7) + ((lane >> 4) << 3);
    const uint32_t bkoff = ((lane >> 3) & 1) << 4;
    const int mw = w << 4;

    // ---- stage 1: 4 K-chunks, B reg-prefetch + tail STS, 1 sync/chunk ----
    #pragma unroll
    for (int c = 0; c < 4; c++) {
        uint4 pb0, pb1, pb2, pb3, pb4;
        if (c < 3) {   // LDG B(c+1) into regs (latency hidden by MMA below)
            const __nv_bfloat16* bsrc = d_w1ctb + (c + 1)*128;
            int iq = t;
            if (iq < 2432) { int r = iq >> 4, c16 = iq & 15; pb0 = *(const uint4*)(bsrc + r*ED + c16*8); }
            iq = 512 + t;  { int r = iq >> 4, c16 = iq & 15; pb1 = *(const uint4*)(bsrc + r*ED + c16*8); }
            iq = 1024 + t; { int r = iq >> 4, c16 = iq & 15; pb2 = *(const uint4*)(bsrc + r*ED + c16*8); }
            iq = 1536 + t; { int r = iq >> 4, c16 = iq & 15; pb3 = *(const uint4*)(bsrc + r*ED + c16*8); }
            iq = 2048 + t;
            if (iq < 2432) { int r = iq >> 4, c16 = iq & 15; pb4 = *(const uint4*)(bsrc + r*ED + c16*8); }
        }
        const uint32_t Ba = smem_u32(Bp[c & 1]);
        #pragma unroll
        for (int ks = 0; ks < 8; ks++) {
            const int eb = c*256 + ks*32;
            uint32_t gi0 = *(const uint32_t*)(gip + eb);
            uint32_t gi1 = *(const uint32_t*)(gip + eb + 16);
            uint32_t ga0 = *(const uint32_t*)(gjAp + eb);
            uint32_t ga1 = *(const uint32_t*)(gjAp + eb + 16);
            uint32_t gb0 = *(const uint32_t*)(gjBp + eb);
            uint32_t gb1 = *(const uint32_t*)(gjBp + eb + 16);
            uint32_t a0 = mulbf2(gi0, ga0);
            uint32_t a1 = mulbf2(gi0, gb0);
            uint32_t a2 = mulbf2(gi1, ga1);
            uint32_t a3 = mulbf2(gi1, gb1);
            uint32_t bb = Ba + brow*P1 + bkoff + ks*32;
            #pragma unroll
            for (int np = 0; np < 9; np++) {
                uint32_t b0, b1r, b2r, b3r;
                ldsm_x4(b0, b1r, b2r, b3r, bb + np*(16*P1));
                mma16816(acc[2*np],     a0, a1, a2, a3, b0, b1r);
                mma16816(acc[2*np + 1], a0, a1, a2, a3, b2r, b3r);
            }
            uint32_t b0, b1r;
            ldsm_x2(b0, b1r, Ba + (144 + (lane & 7))*P1 + bkoff + ks*32);
            mma16816(acc[18], a0, a1, a2, a3, b0, b1r);
        }
        if (c < 3) {   // STS into other buffer (its readers finished before chunk c began)
            char* Bd = Bp[(c + 1) & 1];
            int idx = t;
            if (idx < 2432) { int r = idx >> 4, c16 = idx & 15; *(uint4*)(Bd + r*P1 + c16*16) = pb0; }
            idx = 512 + t;  { int r = idx >> 4, c16 = idx & 15; *(uint4*)(Bd + r*P1 + c16*16) = pb1; }
            idx = 1024 + t; { int r = idx >> 4, c16 = idx & 15; *(uint4*)(Bd + r*P1 + c16*16) = pb2; }
            idx = 1536 + t; { int r = idx >> 4, c16 = idx & 15; *(uint4*)(Bd + r*P1 + c16*16) = pb3; }
            idx = 2048 + t;
            if (idx < 2432) { int r = idx >> 4, c16 = idx & 15; *(uint4*)(Bd + r*P1 + c16*16) = pb4; }
        }
        __syncthreads();
    }

    // ---- epilogue 1: hA frags in regs; hB -> HtB; W2 -> W2s ----
    uint32_t hA[19][2];
    {
        #pragma unroll
        for (int q = 0; q < 6; q++) {
            int idx = q*512 + t;
            if (idx < HP*19) {
                int row = idx / 19, c16 = idx - row*19;
                *(uint4*)(W2s + row*PH + c16*16) = *(const uint4*)(d_w2t + row*HP + c16*8);
            }
        }
        const __nv_bfloat16* hiIr = his + w*HP;
        const __nv_bfloat16* hjIr = hjs + w*HP;
        const int jlo = lane >> 2, jhi = jlo + 8;
        const __nv_bfloat16* hjJl = hjs + (16 + jlo)*HP;
        const __nv_bfloat16* hjJh = hjs + (16 + jhi)*HP;
        const __nv_bfloat16* hiJl = his + (16 + jlo)*HP;
        const __nv_bfloat16* hiJh = his + (16 + jhi)*HP;
        char* rowBlo = HtB + (mw + jlo)*PH;
        char* rowBhi = HtB + (mw + jhi)*PH;
        #pragma unroll
        for (int nt = 0; nt < 19; nt++) {
            int col = nt*8 + (lane & 3)*2;
            float2 hiI = bf2_to_f2(*(const uint32_t*)(hiIr + col));
            float2 hjl = bf2_to_f2(*(const uint32_t*)(hjJl + col));
            float2 hjh = bf2_to_f2(*(const uint32_t*)(hjJh + col));
            hA[nt][0] = pack_bf2(fmaxf(acc[nt][0] + hiI.x + hjl.x, 0.f),
                                 fmaxf(acc[nt][1] + hiI.y + hjl.y, 0.f));
            hA[nt][1] = pack_bf2(fmaxf(acc[nt][2] + hiI.x + hjh.x, 0.f),
                                 fmaxf(acc[nt][3] + hiI.y + hjh.y, 0.f));
            if (!diag) {
                float2 hjI = bf2_to_f2(*(const uint32_t*)(hjIr + col));
                float2 hil = bf2_to_f2(*(const uint32_t*)(hiJl + col));
                float2 hih = bf2_to_f2(*(const uint32_t*)(hiJh + col));
                *(uint32_t*)(rowBlo + col*2) =
                    pack_bf2(fmaxf(acc[nt][0] + hil.x + hjI.x, 0.f),
                             fmaxf(acc[nt][1] + hil.y + hjI.y, 0.f));
                *(uint32_t*)(rowBhi + col*2) =
                    pack_bf2(fmaxf(acc[nt][2] + hih.x + hjI.x, 0.f),
                             fmaxf(acc[nt][3] + hih.y + hjI.y, 0.f));
            }
        }
    }
    __syncthreads();   // W2s + HtB ready

    // ---- merged stage 2: passes A and B share W2 fragments ----
    const uint32_t W2a  = smem_u32(W2s);
    const uint32_t HtBa = smem_u32(HtB);
    const uint32_t aoffH = (mw + (lane & 15))*PH + ((lane >> 4) << 4);
    const float b3v = b3[0];

    float slA = 0.f, shA = 0.f, slB = 0.f, shB = 0.f;
    #pragma unroll
    for (int hf = 0; hf < 2; hf++) {
        float aA[10][4], aB[10][4];
        #pragma unroll
        for (int n = 0; n < 10; n++)
            #pragma unroll
            for (int k = 0; k < 4; k++) { aA[n][k] = 0.f; aB[n][k] = 0.f; }

        #pragma unroll
        for (int ks = 0; ks < 9; ks++) {
            uint32_t a0 = hA[2*ks][0],     a1 = hA[2*ks][1];
            uint32_t a2 = hA[2*ks + 1][0], a3 = hA[2*ks + 1][1];
            uint32_t c0 = 0, c1 = 0, c2 = 0, c3 = 0;
            if (!diag) ldsm_x4(c0, c1, c2, c3, HtBa + aoffH + ks*32);
            if (hf == 0) {
                uint32_t bb = W2a + brow*PH + bkoff + ks*32;
                #pragma unroll
                for (int np = 0; np < 5; np++) {
                    uint32_t b0, b1r, b2r, b3r;
                    ldsm_x4(b0, b1r, b2r, b3r, bb + np*(16*PH));
                    mma16816(aA[2*np],     a0, a1, a2, a3, b0, b1r);
                    mma16816(aA[2*np + 1], a0, a1, a2, a3, b2r, b3r);
                    if (!diag) {
                        mma16816(aB[2*np],     c0, c1, c2, c3, b0, b1r);
                        mma16816(aB[2*np + 1], c0, c1, c2, c3, b2r, b3r);
                    }
                }
            } else {
                uint32_t bb = W2a + (80 + brow)*PH + bkoff + ks*32;
                #pragma unroll
                for (int np = 0; np < 4; np++) {
                    uint32_t b0, b1r, b2r, b3r;
                    ldsm_x4(b0, b1r, b2r, b3r, bb + np*(16*PH));
                    mma16816(aA[2*np],     a0, a1, a2, a3, b0, b1r);
                    mma16816(aA[2*np + 1], a0, a1, a2, a3, b2r, b3r);
                    if (!diag) {
                        mma16816(aB[2*np],     c0, c1, c2, c3, b0, b1r);
                        mma16816(aB[2*np + 1], c0, c1, c2, c3, b2r, b3r);
                    }
                }
                uint32_t b0, b1r;
                ldsm_x2(b0, b1r, W2a + (144 + (lane & 7))*PH + bkoff + ks*32);
                mma16816(aA[8], a0, a1, a2, a3, b0, b1r);
                if (!diag) mma16816(aB[8], c0, c1, c2, c3, b0, b1r);
            }
        }
        {   // k8 tail (cols 144-151, byte 288)
            uint32_t ta0 = hA[18][0], ta1 = hA[18][1];
            uint32_t tc0 = 0, tc1 = 0;
            if (!diag) ldsm_x2(tc0, tc1, HtBa + (mw + (lane & 15))*PH + 288);
            if (hf == 0) {
                #pragma unroll
                for (int q = 0; q < 2; q++) {
                    uint32_t b0, b1r, b2r, b3r;
                    ldsm_x4(b0, b1r, b2r, b3r,
                            W2a + (uint32_t)((q*32 + (lane >> 3)*8 + (lane & 7))*PH + 288));
                    mma16808(aA[4*q + 0], ta0, ta1, b0);
                    mma16808(aA[4*q + 1], ta0, ta1, b1r);
                    mma16808(aA[4*q + 2], ta0, ta1, b2r);
                    mma16808(aA[4*q + 3], ta0, ta1, b3r);
                    if (!diag) {
                        mma16808(aB[4*q + 0], tc0, tc1, b0);
                        mma16808(aB[4*q + 1], tc0, tc1, b1r);
                        mma16808(aB[4*q + 2], tc0, tc1, b2r);
                        mma16808(aB[4*q + 3], tc0, tc1, b3r);
                    }
                }
                uint32_t b0, b1r;
                ldsm_x2(b0, b1r,
                        W2a + (uint32_t)((64 + ((lane >> 3) & 1)*8 + (lane & 7))*PH + 288));
                mma16808(aA[8], ta0, ta1, b0);
                mma16808(aA[9], ta0, ta1, b1r);
                if (!diag) {
                    mma16808(aB[8], tc0, tc1, b0);
                    mma16808(aB[9], tc0, tc1, b1r);
                }
            } else {
                #pragma unroll
                for (int q = 0; q < 2; q++) {
                    uint32_t b0, b1r, b2r, b3r;
                    ldsm_x4(b0, b1r, b2r, b3r,
                            W2a + (uint32_t)((80 + q*32 + (lane >> 3)*8 + (lane & 7))*PH + 288));
                    mma16808(aA[4*q + 0], ta0, ta1, b0);
                    mma16808(aA[4*q + 1], ta0, ta1, b1r);
                    mma16808(aA[4*q + 2], ta0, ta1, b2r);
                    mma16808(aA[4*q + 3], ta0, ta1, b3r);
                    if (!diag) {
                        mma16808(aB[4*q + 0], tc0, tc1, b0);
                        mma16808(aB[4*q + 1], tc0, tc1, b1r);
                        mma16808(aB[4*q + 2], tc0, tc1, b2r);
                        mma16808(aB[4*q + 3], tc0, tc1, b3r);
                    }
                }
                uint32_t bx;
                ldsm_x1(bx, W2a + (uint32_t)((144 + (lane & 7))*PH + 288));
                mma16808(aA[8], ta0, ta1, bx);
                if (!diag) mma16808(aB[8], tc0, tc1, bx);
            }
        }
        const int ntl = hf ? 9 : 10;
        #pragma unroll
        for (int nt = 0; nt < 10; nt++) {
            if (nt >= ntl) break;
            int col = hf*80 + nt*8 + (lane & 3)*2;
            float w0 = w3s[col], w1 = w3s[col + 1];
            float z0 = b2s[col], z1 = b2s[col + 1];
            slA = fmaf(fmaxf(aA[nt][0] + z0, 0.f), w0, slA);
            slA = fmaf(fmaxf(aA[nt][1] + z1, 0.f), w1, slA);
            shA = fmaf(fmaxf(aA[nt][2] + z0, 0.f), w0, shA);
            shA = fmaf(fmaxf(aA[nt][3] + z1, 0.f), w1, shA);
            if (!diag) {
                slB = fmaf(fmaxf(aB[nt][0] + z0, 0.f), w0, slB);
                slB = fmaf(fmaxf(aB[nt][1] + z1, 0.f), w1, slB);
                shB = fmaf(fmaxf(aB[nt][2] + z0, 0.f), w0, shB);
                shB = fmaf(fmaxf(aB[nt][3] + z1, 0.f), w1, shB);
            }
        }
    }
    slA += __shfl_xor_sync(0xFFFFFFFF, slA, 1);
    slA += __shfl_xor_sync(0xFFFFFFFF, slA, 2);
    shA += __shfl_xor_sync(0xFFFFFFFF, shA, 1);
    shA += __shfl_xor_sync(0xFFFFFFFF, shA, 2);
    if (!diag) {
        slB += __shfl_xor_sync(0xFFFFFFFF, slB, 1);
        slB += __shfl_xor_sync(0xFFFFFFFF, slB, 2);
        shB += __shfl_xor_sync(0xFFFFFFFF, shB, 1);
        shB += __shfl_xor_sync(0xFFFFFFFF, shB, 2);
    }
    if ((lane & 3) == 0) {
        int jlo = lane >> 2, jhi = jlo + 8;
        out[(size_t)(b*NQ + i0 + w)*NQ + j0 + jlo] =
            (mIs[w] + mJs[jlo] + slA + b3v) * (1.0f/3.0f);
        out[(size_t)(b*NQ + i0 + w)*NQ + j0 + jhi] =
            (mIs[w] + mJs[jhi] + shA + b3v) * (1.0f/3.0f);
        if (!diag) {
            out[(size_t)(b*NQ + j0 + jlo)*NQ + i0 + w] =
                (mIs[w] + mJs[jlo] + slB + b3v) * (1.0f/3.0f);
            out[(size_t)(b*NQ + j0 + jhi)*NQ + i0 + w] =
                (mIs[w] + mJs[jhi] + shB + b3v) * (1.0f/3.0f);
        }
    }
}

// ---------------------------------------------------------------------------
extern "C" void kernel_launch(void* const* d_in, const int* in_sizes, int n_in,
                              void* d_out, int out_size) {
    const float* g  = (const float*)d_in[0];
    const float* m  = (const float*)d_in[1];
    const float* W1 = (const float*)d_in[2];
    const float* b1 = (const float*)d_in[3];
    const float* W2 = (const float*)d_in[4];
    const float* b2 = (const float*)d_in[5];
    const float* W3 = (const float*)d_in[6];
    const float* b3 = (const float*)d_in[7];
    float* out = (float*)d_out;

    cudaFuncSetAttribute(pair_frag3_kernel,
                         cudaFuncAttributeMaxDynamicSharedMemorySize, SMEM_BYTES);

    prep_w1ct<<<dim3(ED/32, 5), dim3(32, 32)>>>(W1);
    prep_w2t<<<HP, HP>>>(W2);
    prep_hihj<<<dim3(NQ/8, BB, 2), dim3(160, 4)>>>(g, W1, b1);
    pair_frag3_kernel<<<dim3(136, BB), 512, SMEM_BYTES>>>(g, m, b2, W3, b3, out);
}